// round 16
// baseline (speedup 1.0000x reference)
#include <cuda_runtime.h>
#include <float.h>

// YOLOv3 detection-head decode, fused single pass. One thread per cell.
//
// R15 resubmit (R14/15 bench was an infra failure: container died, kernel
// never ran). Pin-size bisect on the R13 skeleton.
// Measured pin curve: 64MiB=14.91us, 80MiB=14.40us, 84MiB=14.75us ->
// stable-pin optimum inside (80, 84); this probes 82MiB.
// Skeleton: 32 regs / ~58 warps/SM / MLP-8 batches (tied 48-warp/MLP-16 at
// 14.40; occupancy x MLP axis saturated — plateau is cross-CTA L1tex-queue
// contention, common to both configs).
//
// Range policy: [x, x+82MiB) evict_last (deterministic, address-based ->
// stable L2-resident set across graph replays), trailing input evict_first.
// Outputs are __stcs (evict-first) so they never displace pinned input.
//
// Algebraic simplification: sigmoid is monotonic ->
//   max(sigmoid(cls)) == sigmoid(max(cls)), argmax(sigmoid(cls)) == argmax(cls).

#define HWV     5776      // 76*76
#define WV      76
#define HV      76
#define ATTRS   85
#define NCLS    80
#define NMASK   3
#define VAL_CONF 0.1f
#define PIN_BYTES (82u * 1024u * 1024u)   // pinned evict_last prefix of input

__device__ __forceinline__ float sigmoidf(float v) {
    return 1.0f / (1.0f + __expf(-v));
}

// Range cache policy: [x, x+primary) evict_last, [x+primary, x+total) evict_first.
__device__ __forceinline__ unsigned long long mk_range_policy(
    const float* __restrict__ base, unsigned int primary, unsigned int total) {
    unsigned long long pol;
    asm("createpolicy.range.global.L2::evict_last.L2::evict_first.b64 %0, [%1], %2, %3;"
        : "=l"(pol) : "l"(base), "r"(primary), "r"(total));
    return pol;
}

// Read-only scalar load with the range policy applied.
__device__ __forceinline__ float ldg_pol(const float* __restrict__ p,
                                         unsigned long long pol) {
    float v;
    asm("ld.global.nc.L2::cache_hint.f32 %0, [%1], %2;"
        : "=f"(v) : "l"(p), "l"(pol));
    return v;
}

__global__ void __launch_bounds__(128, 16)
yolo_head_kernel(const float* __restrict__ x,
                 const float* __restrict__ anchors,
                 float* __restrict__ out,
                 int ncells,             // nplanes * HWV
                 long long pred_elems,   // nplanes * HWV * 7
                 unsigned int in_bytes)  // total input bytes
{
    __shared__ float sp[4][224];        // per-warp staging: 32 cells x 7 attrs

    int g    = blockIdx.x * blockDim.x + threadIdx.x;   // exact grid: no tail
    int lane = threadIdx.x & 31;
    int wrp  = threadIdx.x >> 5;

    int plane = g / HWV;
    int idx   = g - plane * HWV;        // cell index within plane
    int m     = plane % NMASK;          // anchor/mask index
    int h     = idx / WV;
    int w     = idx - h * WV;

    const float* p = x + (size_t)plane * (ATTRS * HWV) + idx;
    unsigned int primary = (in_bytes < PIN_BYTES) ? in_bytes : PIN_BYTES;
    const unsigned long long pol = mk_range_policy(x, primary, in_bytes);

    // Attributes 0..4 — independent coalesced streams, issued up front.
    float tx = ldg_pol(p + 0 * HWV, pol);
    float ty = ldg_pol(p + 1 * HWV, pol);
    float tw = ldg_pol(p + 2 * HWV, pol);
    float th = ldg_pol(p + 3 * HWV, pol);
    float tc = ldg_pol(p + 4 * HWV, pol);

    // Class max/argmax over raw logits. 8-deep register batches (MLP=8),
    // 2 independent compare chains (even/odd class) — register-lean for the
    // 32-reg / 58-warp configuration. Strict '>' keeps first occurrence
    // within each chain.
    float b0 = -FLT_MAX, b1 = -FLT_MAX;
    int   i0 = 0, i1 = 0;

    #pragma unroll
    for (int a0 = 0; a0 < NCLS; a0 += 8) {
        float v[8];
        #pragma unroll
        for (int j = 0; j < 8; j++)
            v[j] = ldg_pol(p + (size_t)(5 + a0 + j) * HWV, pol);
        #pragma unroll
        for (int j = 0; j < 8; j += 2) {
            int a = a0 + j;
            if (v[j + 0] > b0) { b0 = v[j + 0]; i0 = a;     }
            if (v[j + 1] > b1) { b1 = v[j + 1]; i1 = a + 1; }
        }
    }

    // Exact first-occurrence merge (matches jnp.argmax tie-break).
    float best = b0; int bidx = i0;
    if (b1 > best || (b1 == best && i1 < bidx)) { best = b1; bidx = i1; }

    float aw = __ldg(&anchors[2 * m + 0]);
    float ah = __ldg(&anchors[2 * m + 1]);

    const float invW = 1.0f / (float)WV;
    const float invH = 1.0f / (float)HV;

    float cx   = (sigmoidf(tx) + (float)w) * invW;
    float cy   = (sigmoidf(ty) + (float)h) * invH;
    float bw   = __expf(tw) * aw;
    float bh   = __expf(th) * ah;
    float conf = sigmoidf(tc);
    float cls  = sigmoidf(best);
    float s    = (conf > VAL_CONF) ? 1.0f : 0.0f;

    // Stage 7 outputs in smem (stride-7: gcd(7,32)=1 -> conflict-free).
    float* sw_ = sp[wrp];
    sw_[lane * 7 + 0] = (cx - bw * 0.5f) * s;
    sw_[lane * 7 + 1] = (cy - bh * 0.5f) * s;
    sw_[lane * 7 + 2] = (cx + bw * 0.5f) * s;
    sw_[lane * 7 + 3] = (cy + bh * 0.5f) * s;
    sw_[lane * 7 + 4] = conf * s;
    sw_[lane * 7 + 5] = cls * s;
    sw_[lane * 7 + 6] = (float)bidx * s;
    __syncwarp();

    // Coalesced float4 writeback of the warp's contiguous 896B pred region
    // (896 = 7*128 -> warp base is 128B aligned). Evict-first stores.
    int gbase = g - lane;               // first cell of this warp
    float* obase = out + (long long)gbase * 7;
    #pragma unroll
    for (int j = lane; j < 56; j += 32) {
        float4 v4 = *(const float4*)&sw_[j * 4];
        __stcs((float4*)(obase + j * 4), v4);
    }

    __stcs(&out[pred_elems + g], s);
}

extern "C" void kernel_launch(void* const* d_in, const int* in_sizes, int n_in,
                              void* d_out, int out_size)
{
    const float* x       = (const float*)d_in[0];
    const float* anchors = (const float*)d_in[1];
    float*       out     = (float*)d_out;

    int nplanes = in_sizes[0] / (ATTRS * HWV);          // bs * 3
    int ncells  = nplanes * HWV;                        // 277248
    long long pred_elems = (long long)ncells * 7;
    unsigned int in_bytes = (unsigned int)in_sizes[0] * 4u;

    int block = 128;
    int grid  = ncells / block;                         // 2166, exact
    yolo_head_kernel<<<grid, block>>>(x, anchors, out, ncells, pred_elems, in_bytes);
}